// round 2
// baseline (speedup 1.0000x reference)
#include <cuda_runtime.h>
#include <cstdint>

#define Bn 2
#define Cc 64
#define Hh 192
#define Ww 192
#define HWp (Hh*Ww)
#define NOFF 72
#define NEXP 256

// Scratch: offset field t (B, 72, H, W) = 21.2 MB
__device__ float g_t[(size_t)Bn * NOFF * HWp];

// ---------------------------------------------------------------------------
// Kernel 1: offset branch.
// t[b,r,h,w] = b2[r] + sum_{c,j,k} w2[r,4c+j] * w1[4c+j,k] * (xs(c,k) - x[c])
// One thread per pixel, full row per block (192 threads). 72 accumulators in
// registers; w1/w2/b2 staged in dynamic smem (uniform broadcast LDS.128).
// ---------------------------------------------------------------------------
__global__ void __launch_bounds__(192, 2) offsets_kernel(
    const float* __restrict__ x, const float* __restrict__ w1,
    const float* __restrict__ w2, const float* __restrict__ b2)
{
    extern __shared__ float sm1[];
    float* w2s = sm1;                    // 72*256
    float* w1s = sm1 + NOFF * NEXP;      // 256*9
    float* b2s = w1s + NEXP * 9;         // 72

    const int tid = threadIdx.x;
    for (int i = tid; i < NOFF * NEXP; i += 192) w2s[i] = w2[i];
    for (int i = tid; i < NEXP * 9;   i += 192) w1s[i] = w1[i];
    if (tid < NOFF) b2s[tid] = b2[tid];
    __syncthreads();

    const int w = tid;
    const int h = blockIdx.x;
    const int b = blockIdx.y;

    float tacc[NOFF];
    #pragma unroll
    for (int r = 0; r < NOFF; r++) tacc[r] = b2s[r];

    const float* xb = x + (size_t)b * Cc * HWp;
    const float4* w2v = reinterpret_cast<const float4*>(w2s);

    for (int c = 0; c < Cc; c++) {
        const float* xp = xb + c * HWp;
        const float xc = xp[h * Ww + w];
        float d[9];
        #pragma unroll
        for (int k = 0; k < 9; k++) {
            const int yy = h - 1 + k / 3;
            const int xx = w - 1 + k % 3;
            float v = 0.f;
            if (yy >= 0 && yy < Hh && xx >= 0 && xx < Ww)
                v = __ldg(xp + yy * Ww + xx);
            d[k] = v - xc;   // zero-padded conv minus center*wsum == taps of (xs - xc)
        }
        float xd0 = 0.f, xd1 = 0.f, xd2 = 0.f, xd3 = 0.f;
        #pragma unroll
        for (int k = 0; k < 9; k++) {
            xd0 = fmaf(w1s[(4*c + 0) * 9 + k], d[k], xd0);
            xd1 = fmaf(w1s[(4*c + 1) * 9 + k], d[k], xd1);
            xd2 = fmaf(w1s[(4*c + 2) * 9 + k], d[k], xd2);
            xd3 = fmaf(w1s[(4*c + 3) * 9 + k], d[k], xd3);
        }
        #pragma unroll
        for (int r = 0; r < NOFF; r++) {
            const float4 wv = w2v[r * 64 + c];  // w2s[r*256 + 4c .. +3]
            tacc[r] = fmaf(wv.x, xd0, tacc[r]);
            tacc[r] = fmaf(wv.y, xd1, tacc[r]);
            tacc[r] = fmaf(wv.z, xd2, tacc[r]);
            tacc[r] = fmaf(wv.w, xd3, tacc[r]);
        }
    }

    float* tp = g_t + (size_t)b * NOFF * HWp + h * Ww + w;
    #pragma unroll
    for (int r = 0; r < NOFF; r++) tp[(size_t)r * HWp] = tacc[r];
}

// ---------------------------------------------------------------------------
// Kernel 2: deformable depthwise conv + center subtraction + 64x64 1x1.
// Block = 32-pixel row segment, 256 threads (8 warps).
// Phase 1: 36 (group,tap) bilinear weight/index sets -> smem (computed once).
// Phase 2: warp wa samples channels wa*8..wa*8+7; lanes = pixels (gathers hit
//          few L1 lines since offsets vary smoothly along a row).
// Phase 3: 64x64 matvec from smem (ys conflict-free, weights broadcast f4).
// ---------------------------------------------------------------------------
__global__ void __launch_bounds__(256) deform_kernel(
    const float* __restrict__ x, const float* __restrict__ wdef,
    const float* __restrict__ wout, float* __restrict__ out_m)
{
    extern __shared__ char sm2[];
    float4* swv   = (float4*)sm2;                              // 36*32*16 = 18432
    int4*   siv   = (int4*)(sm2 + 18432);                      // 18432
    float*  woT   = (float*)(sm2 + 36864);                     // 64*64*4 = 16384 (transposed)
    float*  ys    = (float*)(sm2 + 36864 + 16384);             // 64*32*4 = 8192
    float*  wdefs = (float*)(sm2 + 36864 + 16384 + 8192);      // 576*4
    float*  wdsum = wdefs + 576;                               // 64*4

    const int tid  = threadIdx.x;
    const int lane = tid & 31;
    const int wa   = tid >> 5;
    const int w0   = blockIdx.x * 32;
    const int h    = blockIdx.y;
    const int b    = blockIdx.z;

    // Stage weights
    for (int i = tid; i < 64 * 64; i += 256) {
        const int o = i >> 6, c = i & 63;
        woT[c * 64 + o] = wout[i];
    }
    for (int i = tid; i < 576; i += 256) wdefs[i] = wdef[i];
    if (tid < 64) {
        float s = 0.f;
        #pragma unroll
        for (int k = 0; k < 9; k++) s += wdef[tid * 9 + k];
        wdsum[tid] = s;
    }

    // Phase 1: bilinear parameters for 36 (group,tap) items x 32 pixels
    const float* tb = g_t + (size_t)b * NOFF * HWp + h * Ww + w0;
    for (int it = wa; it < 36; it += 8) {
        const int k = it % 9;   // it = g*9 + k
        const float dy = tb[(size_t)(it * 2)     * HWp + lane];
        const float dx = tb[(size_t)(it * 2 + 1) * HWp + lane];
        const float py = (float)(h - 1 + k / 3) + dy;
        const float px = (float)(w0 + lane - 1 + k % 3) + dx;
        const float y0f = floorf(py), x0f = floorf(px);
        const float wy = py - y0f, wx = px - x0f;
        const int iy0 = (int)y0f, ix0 = (int)x0f;
        const int iy1 = iy0 + 1,  ix1 = ix0 + 1;
        const bool vy0 = (iy0 >= 0) && (iy0 < Hh);
        const bool vy1 = (iy1 >= 0) && (iy1 < Hh);
        const bool vx0 = (ix0 >= 0) && (ix0 < Ww);
        const bool vx1 = (ix1 >= 0) && (ix1 < Ww);
        float4 wv;
        wv.x = (vy0 && vx0) ? (1.f - wy) * (1.f - wx) : 0.f;
        wv.y = (vy0 && vx1) ? (1.f - wy) * wx         : 0.f;
        wv.z = (vy1 && vx0) ? wy * (1.f - wx)         : 0.f;
        wv.w = (vy1 && vx1) ? wy * wx                 : 0.f;
        const int cy0 = min(max(iy0, 0), Hh - 1), cy1 = min(max(iy1, 0), Hh - 1);
        const int cx0 = min(max(ix0, 0), Ww - 1), cx1 = min(max(ix1, 0), Ww - 1);
        int4 iv;
        iv.x = cy0 * Ww + cx0;  iv.y = cy0 * Ww + cx1;
        iv.z = cy1 * Ww + cx0;  iv.w = cy1 * Ww + cx1;
        swv[it * 32 + lane] = wv;
        siv[it * 32 + lane] = iv;
    }
    __syncthreads();

    // Phase 2: gather + depthwise accumulation, 8 channels per warp
    const int pix = h * Ww + w0 + lane;
    #pragma unroll
    for (int i = 0; i < 8; i++) {
        const int c = wa * 8 + i;
        const int g = c >> 4;                 // deform group (Cg = 16)
        const float* bp = x + ((size_t)b * Cc + c) * HWp;
        float acc = 0.f;
        #pragma unroll
        for (int k = 0; k < 9; k++) {
            const int it = g * 9 + k;
            const float4 wv = swv[it * 32 + lane];
            const int4   iv = siv[it * 32 + lane];
            float v = wv.x * __ldg(bp + iv.x);
            v = fmaf(wv.y, __ldg(bp + iv.y), v);
            v = fmaf(wv.z, __ldg(bp + iv.z), v);
            v = fmaf(wv.w, __ldg(bp + iv.w), v);
            acc = fmaf(wdefs[c * 9 + k], v, acc);
        }
        const float xc = __ldg(bp + pix);
        ys[c * 32 + lane] = fmaf(-xc, wdsum[c], acc);
    }
    __syncthreads();

    // Phase 3: m[o] = sum_c wout[o,c] * y[c]; warp wa computes o = wa*8..wa*8+7
    float macc[8];
    #pragma unroll
    for (int j = 0; j < 8; j++) macc[j] = 0.f;
    const float4* woT4 = (const float4*)woT;
    #pragma unroll 8
    for (int c = 0; c < 64; c++) {
        const float yv = ys[c * 32 + lane];
        const float4 a  = woT4[c * 16 + wa * 2];
        const float4 bq = woT4[c * 16 + wa * 2 + 1];
        macc[0] = fmaf(a.x,  yv, macc[0]);
        macc[1] = fmaf(a.y,  yv, macc[1]);
        macc[2] = fmaf(a.z,  yv, macc[2]);
        macc[3] = fmaf(a.w,  yv, macc[3]);
        macc[4] = fmaf(bq.x, yv, macc[4]);
        macc[5] = fmaf(bq.y, yv, macc[5]);
        macc[6] = fmaf(bq.z, yv, macc[6]);
        macc[7] = fmaf(bq.w, yv, macc[7]);
    }
    #pragma unroll
    for (int j = 0; j < 8; j++)
        out_m[((size_t)b * Cc + wa * 8 + j) * HWp + pix] = macc[j];
}

extern "C" void kernel_launch(void* const* d_in, const int* in_sizes, int n_in,
                              void* d_out, int out_size)
{
    const float* x1     = (const float*)d_in[0];
    const float* w_off1 = (const float*)d_in[1];
    const float* w_off2 = (const float*)d_in[2];
    const float* b_off2 = (const float*)d_in[3];
    const float* w_def  = (const float*)d_in[4];
    const float* w_out  = (const float*)d_in[5];
    float* out = (float*)d_out;

    const size_t N = (size_t)Bn * Cc * HWp;   // 4,718,592
    const int SMEM1 = (NOFF * NEXP + NEXP * 9 + NOFF) * 4;          // 83,232 B
    const int SMEM2 = 18432 + 18432 + 16384 + 8192 + 576*4 + 64*4;  // 64,000 B

    cudaFuncSetAttribute(offsets_kernel, cudaFuncAttributeMaxDynamicSharedMemorySize, SMEM1);
    cudaFuncSetAttribute(deform_kernel,  cudaFuncAttributeMaxDynamicSharedMemorySize, SMEM2);

    // Output = (x1, m): passthrough copy of x1 into first half
    cudaMemcpyAsync(out, x1, N * sizeof(float), cudaMemcpyDeviceToDevice, 0);

    offsets_kernel<<<dim3(Hh, Bn), 192, SMEM1>>>(x1, w_off1, w_off2, b_off2);
    deform_kernel<<<dim3(Ww / 32, Hh, Bn), 256, SMEM2>>>(x1, w_def, w_out, out + N);
}

// round 4
// speedup vs baseline: 1.0728x; 1.0728x over previous
#include <cuda_runtime.h>
#include <cstdint>

#define Bn 2
#define Cc 64
#define Hh 192
#define Ww 192
#define HWp (Hh*Ww)
#define NOFF 72
#define NEXP 256

// Scratch: offset field t (B, 72, H, W) = 21.2 MB
__device__ float g_t[(size_t)Bn * NOFF * HWp];
// Transposed 1x1 output weights: woT[c][o]
__device__ float g_woT[Cc * Cc];

// ---------------------------------------------------------------------------
// Kernel 0: transpose wout (64x64) once into a device global.
// ---------------------------------------------------------------------------
__global__ void transpose_wout_kernel(const float* __restrict__ wout)
{
    const int i = blockIdx.x * 256 + threadIdx.x;
    if (i < Cc * Cc) {
        const int o = i >> 6, c = i & 63;
        g_woT[c * Cc + o] = wout[i];
    }
}

// ---------------------------------------------------------------------------
// Kernel 1: offset branch.
// t[b,r,h,w] = b2[r] + sum_{c,j,k} w2[r,4c+j] * w1[4c+j,k] * (xs(c,k) - x[c])
// 96-thread half-row blocks (grid 768) for fine load balance; w2/b2 in smem
// (74KB -> 3 blocks/SM); w1 via warp-uniform broadcast __ldg.
// ---------------------------------------------------------------------------
__global__ void __launch_bounds__(96) offsets_kernel(
    const float* __restrict__ x, const float* __restrict__ w1,
    const float* __restrict__ w2, const float* __restrict__ b2)
{
    extern __shared__ float sm1[];
    float* w2s = sm1;                    // 72*256
    float* b2s = sm1 + NOFF * NEXP;      // 72

    const int tid = threadIdx.x;
    for (int i = tid; i < NOFF * NEXP; i += 96) w2s[i] = w2[i];
    if (tid < NOFF) b2s[tid] = b2[tid];
    __syncthreads();

    const int w = blockIdx.x * 96 + tid;
    const int h = blockIdx.y;
    const int b = blockIdx.z;

    float tacc[NOFF];
    #pragma unroll
    for (int r = 0; r < NOFF; r++) tacc[r] = b2s[r];

    const float* xb = x + (size_t)b * Cc * HWp;
    const float4* w2v = reinterpret_cast<const float4*>(w2s);

    for (int c = 0; c < Cc; c++) {
        const float* xp = xb + c * HWp;
        const float xc = xp[h * Ww + w];
        float d[9];
        #pragma unroll
        for (int k = 0; k < 9; k++) {
            const int yy = h - 1 + k / 3;
            const int xx = w - 1 + k % 3;
            float v = 0.f;
            if (yy >= 0 && yy < Hh && xx >= 0 && xx < Ww)
                v = __ldg(xp + yy * Ww + xx);
            d[k] = v - xc;   // zero-padded conv minus center*wsum == taps of (xs - xc)
        }
        const float* w1c = w1 + 4 * c * 9;   // warp-uniform broadcast reads
        float xd0 = 0.f, xd1 = 0.f, xd2 = 0.f, xd3 = 0.f;
        #pragma unroll
        for (int k = 0; k < 9; k++) {
            xd0 = fmaf(__ldg(w1c + k),      d[k], xd0);
            xd1 = fmaf(__ldg(w1c +  9 + k), d[k], xd1);
            xd2 = fmaf(__ldg(w1c + 18 + k), d[k], xd2);
            xd3 = fmaf(__ldg(w1c + 27 + k), d[k], xd3);
        }
        #pragma unroll
        for (int r = 0; r < NOFF; r++) {
            const float4 wv = w2v[r * 64 + c];  // w2s[r*256 + 4c .. +3]
            tacc[r] = fmaf(wv.x, xd0, tacc[r]);
            tacc[r] = fmaf(wv.y, xd1, tacc[r]);
            tacc[r] = fmaf(wv.z, xd2, tacc[r]);
            tacc[r] = fmaf(wv.w, xd3, tacc[r]);
        }
    }

    float* tp = g_t + (size_t)b * NOFF * HWp + h * Ww + w;
    #pragma unroll
    for (int r = 0; r < NOFF; r++) tp[(size_t)r * HWp] = tacc[r];
}

// ---------------------------------------------------------------------------
// Kernel 2: deformable depthwise conv + center subtraction + 64x64 1x1.
// Block = 32-pixel row segment, 256 threads (8 warps).
// Phase 1: 36 (group,tap) bilinear weight/index sets -> smem (computed once).
// Phase 2: tap-outer / channel-inner: each warp's 8 channels share ONE deform
//          group, so wv/iv are loaded once per tap into registers (8x fewer
//          LDS than channel-outer).
// Phase 3: 64x64 matvec; ys in smem, transposed weights via broadcast __ldg.
// ---------------------------------------------------------------------------
__global__ void __launch_bounds__(256, 4) deform_kernel(
    const float* __restrict__ x, const float* __restrict__ wdef,
    float* __restrict__ out_m)
{
    extern __shared__ char sm2[];
    float4* swv   = (float4*)sm2;                      // 36*32*16 = 18432
    int4*   siv   = (int4*)(sm2 + 18432);              // 18432
    float*  ys    = (float*)(sm2 + 36864);             // 64*32*4  = 8192
    float*  wdefs = (float*)(sm2 + 36864 + 8192);      // 576*4
    float*  wdsum = wdefs + 576;                       // 64*4

    const int tid  = threadIdx.x;
    const int lane = tid & 31;
    const int wa   = tid >> 5;
    const int w0   = blockIdx.x * 32;
    const int h    = blockIdx.y;
    const int b    = blockIdx.z;

    for (int i = tid; i < 576; i += 256) wdefs[i] = wdef[i];
    if (tid < 64) {
        float s = 0.f;
        #pragma unroll
        for (int k = 0; k < 9; k++) s += wdef[tid * 9 + k];
        wdsum[tid] = s;
    }

    // Phase 1: bilinear parameters for 36 (group,tap) items x 32 pixels
    const float* tb = g_t + (size_t)b * NOFF * HWp + h * Ww + w0;
    for (int it = wa; it < 36; it += 8) {
        const int k = it % 9;   // it = g*9 + k
        const float dy = tb[(size_t)(it * 2)     * HWp + lane];
        const float dx = tb[(size_t)(it * 2 + 1) * HWp + lane];
        const float py = (float)(h - 1 + k / 3) + dy;
        const float px = (float)(w0 + lane - 1 + k % 3) + dx;
        const float y0f = floorf(py), x0f = floorf(px);
        const float wy = py - y0f, wx = px - x0f;
        const int iy0 = (int)y0f, ix0 = (int)x0f;
        const int iy1 = iy0 + 1,  ix1 = ix0 + 1;
        const bool vy0 = (iy0 >= 0) && (iy0 < Hh);
        const bool vy1 = (iy1 >= 0) && (iy1 < Hh);
        const bool vx0 = (ix0 >= 0) && (ix0 < Ww);
        const bool vx1 = (ix1 >= 0) && (ix1 < Ww);
        float4 wv;
        wv.x = (vy0 && vx0) ? (1.f - wy) * (1.f - wx) : 0.f;
        wv.y = (vy0 && vx1) ? (1.f - wy) * wx         : 0.f;
        wv.z = (vy1 && vx0) ? wy * (1.f - wx)         : 0.f;
        wv.w = (vy1 && vx1) ? wy * wx                 : 0.f;
        const int cy0 = min(max(iy0, 0), Hh - 1), cy1 = min(max(iy1, 0), Hh - 1);
        const int cx0 = min(max(ix0, 0), Ww - 1), cx1 = min(max(ix1, 0), Ww - 1);
        int4 iv;
        iv.x = cy0 * Ww + cx0;  iv.y = cy0 * Ww + cx1;
        iv.z = cy1 * Ww + cx0;  iv.w = cy1 * Ww + cx1;
        swv[it * 32 + lane] = wv;
        siv[it * 32 + lane] = iv;
    }
    __syncthreads();

    // Phase 2: gather + depthwise accumulation.
    // Warp wa owns channels wa*8..wa*8+7, all in deform group g = wa/2.
    const int g = wa >> 1;
    const int pix = h * Ww + w0 + lane;
    const float* xc0 = x + ((size_t)b * Cc + wa * 8) * HWp;

    float acc[8];
    #pragma unroll
    for (int i = 0; i < 8; i++) acc[i] = 0.f;

    #pragma unroll
    for (int k = 0; k < 9; k++) {
        const int it = g * 9 + k;
        const float4 wv = swv[it * 32 + lane];
        const int4   iv = siv[it * 32 + lane];
        const float* bp = xc0;
        #pragma unroll
        for (int i = 0; i < 8; i++) {
            float v = wv.x * __ldg(bp + iv.x);
            v = fmaf(wv.y, __ldg(bp + iv.y), v);
            v = fmaf(wv.z, __ldg(bp + iv.z), v);
            v = fmaf(wv.w, __ldg(bp + iv.w), v);
            acc[i] = fmaf(wdefs[(wa * 8 + i) * 9 + k], v, acc[i]);
            bp += HWp;
        }
    }
    #pragma unroll
    for (int i = 0; i < 8; i++) {
        const int c = wa * 8 + i;
        const float xc = __ldg(xc0 + (size_t)i * HWp + pix);
        ys[c * 32 + lane] = fmaf(-xc, wdsum[c], acc[i]);
    }
    __syncthreads();

    // Phase 3: m[o] = sum_c wout[o,c] * y[c]; warp wa computes o = wa*8..wa*8+7
    float macc[8];
    #pragma unroll
    for (int j = 0; j < 8; j++) macc[j] = 0.f;
    const float4* woT4 = (const float4*)g_woT;
    #pragma unroll 8
    for (int c = 0; c < 64; c++) {
        const float yv = ys[c * 32 + lane];
        const float4 a  = __ldg(woT4 + c * 16 + wa * 2);
        const float4 bq = __ldg(woT4 + c * 16 + wa * 2 + 1);
        macc[0] = fmaf(a.x,  yv, macc[0]);
        macc[1] = fmaf(a.y,  yv, macc[1]);
        macc[2] = fmaf(a.z,  yv, macc[2]);
        macc[3] = fmaf(a.w,  yv, macc[3]);
        macc[4] = fmaf(bq.x, yv, macc[4]);
        macc[5] = fmaf(bq.y, yv, macc[5]);
        macc[6] = fmaf(bq.z, yv, macc[6]);
        macc[7] = fmaf(bq.w, yv, macc[7]);
    }
    #pragma unroll
    for (int j = 0; j < 8; j++)
        out_m[((size_t)b * Cc + wa * 8 + j) * HWp + pix] = macc[j];
}

extern "C" void kernel_launch(void* const* d_in, const int* in_sizes, int n_in,
                              void* d_out, int out_size)
{
    const float* x1     = (const float*)d_in[0];
    const float* w_off1 = (const float*)d_in[1];
    const float* w_off2 = (const float*)d_in[2];
    const float* b_off2 = (const float*)d_in[3];
    const float* w_def  = (const float*)d_in[4];
    const float* w_out  = (const float*)d_in[5];
    float* out = (float*)d_out;

    const size_t N = (size_t)Bn * Cc * HWp;   // 4,718,592
    const int SMEM1 = (NOFF * NEXP + NOFF) * 4;            // 74,016 B -> 3 blocks/SM
    const int SMEM2 = 18432 + 18432 + 8192 + 576*4 + 64*4; // 47,616 B -> 4 blocks/SM

    cudaFuncSetAttribute(offsets_kernel, cudaFuncAttributeMaxDynamicSharedMemorySize, SMEM1);
    cudaFuncSetAttribute(deform_kernel,  cudaFuncAttributeMaxDynamicSharedMemorySize, SMEM2);

    // Output = (x1, m): passthrough copy of x1 into first half
    cudaMemcpyAsync(out, x1, N * sizeof(float), cudaMemcpyDeviceToDevice, 0);

    transpose_wout_kernel<<<16, 256>>>(w_out);
    offsets_kernel<<<dim3(2, Hh, Bn), 96, SMEM1>>>(x1, w_off1, w_off2, b_off2);
    deform_kernel<<<dim3(Ww / 32, Hh, Bn), 256, SMEM2>>>(x1, w_def, out + N);
}